// round 6
// baseline (speedup 1.0000x reference)
#include <cuda_runtime.h>
#include <cuda_bf16.h>

// EarthAttention2D v5: full HMMA (projections + QK^T + AV), bf16 hi/lo split.
// One CTA per window. All operands as bf16 hi/lo smem images.

typedef unsigned long long u64;
typedef unsigned int u32;
typedef unsigned short u16;

#define NTOK 72
#define DIMX 192
#define NH 6
#define TOWC 31
#define NWC 30
#define BLK 384
#define NSQ 5184
#define TBLROWS 828

// u32-unit shared offsets
#define U_QH 0        // q / attn-out hi: [72][100]
#define U_QL 7200
#define U_KH 14400    // k hi: [72][100]
#define U_KL 21600
#define U_VTH 28800   // v^T hi: [192][40]  (cols 36-39 = zero pad)
#define U_VTL 36480
#define U_SB 44160    // S f32 [72][72]
#define U_PH 49344    // P hi: [72][41]  (cols 36-39 = zero pad)
#define U_PL 52296
#define U_RS 55248    // 1/rowsum f32 [72]
#define U_TB 55320    // bias slice bf16 [828*6] = 2484 u32
#define SMEM_BYTES (57804 * 4)   // 231216 <= 232448

// Pre-packed W^T A-fragments (hi/lo), register-exact m16n8k16 layout.
// u32 index = ((ct*12 + k)*2 + prec)*128 + lane*4 + r
// ct: 0..11 Q, 12..23 K, 24..35 V, 36..47 out-proj.
__device__ u32 g_wfrag[147456];

// ---------------- helpers ----------------
__device__ __forceinline__ void mma16816(float* d, const u32* a, const u32* b) {
    asm("mma.sync.aligned.m16n8k16.row.col.f32.bf16.bf16.f32 "
        "{%0,%1,%2,%3}, {%4,%5,%6,%7}, {%8,%9}, {%0,%1,%2,%3};"
        : "+f"(d[0]), "+f"(d[1]), "+f"(d[2]), "+f"(d[3])
        : "r"(a[0]), "r"(a[1]), "r"(a[2]), "r"(a[3]), "r"(b[0]), "r"(b[1]));
}
__device__ __forceinline__ u32 packbf(float x0, float x1, u32& lo) {
    __nv_bfloat16 h0 = __float2bfloat16(x0), h1 = __float2bfloat16(x1);
    __nv_bfloat16 l0 = __float2bfloat16(x0 - __bfloat162float(h0));
    __nv_bfloat16 l1 = __float2bfloat16(x1 - __bfloat162float(h1));
    lo = (u32)__bfloat16_as_ushort(l0) | ((u32)__bfloat16_as_ushort(l1) << 16);
    return (u32)__bfloat16_as_ushort(h0) | ((u32)__bfloat16_as_ushort(h1) << 16);
}
__device__ __forceinline__ void bf_split(float v, u32& h, u32& l) {
    __nv_bfloat16 hb = __float2bfloat16(v);
    h = (u32)__bfloat16_as_ushort(hb);
    l = (u32)__bfloat16_as_ushort(__float2bfloat16(v - __bfloat162float(hb)));
}
__device__ __forceinline__ float tbf(u16 b) {
    return __bfloat162float(__ushort_as_bfloat16(b));
}
__device__ __forceinline__ int posv_of(int e, int s_sh) {
    int p = (e * 60 + s_sh) % NSQ;
    int n2 = p / NTOK, m2 = p - n2 * NTOK;
    int n12 = n2 / 12, m12 = m2 / 12;
    return (n12 + 6 * m12) * 23 + (n2 - n12 * 12) - (m2 - m12 * 12) + 11;
}

// ---------------- pre-kernel: pack W^T fragments (unchanged from R4) ------
__global__ void build_wfrags(const float* __restrict__ wqkv,
                             const float* __restrict__ wout) {
    int idx = blockIdx.x * 256 + threadIdx.x;
    int r    = idx & 3;
    int lane = (idx >> 2) & 31;
    int prec = (idx >> 7) & 1;
    int rest = idx >> 8;
    int k  = rest % 12;
    int ct = rest / 12;
    int g = lane >> 2, tid2 = lane & 3;
    int i  = g + (r & 1) * 8;
    int kk = tid2 * 2 + (r >> 1) * 8;
    int k_abs = k * 16 + kk;
    const float* W; int stride, n_abs;
    if (ct < 36) { W = wqkv; stride = 576; n_abs = ct * 16 + i; }
    else         { W = wout; stride = 192; n_abs = (ct - 36) * 16 + i; }
    float v0 = W[(size_t)k_abs * stride + n_abs];
    float v1 = W[(size_t)(k_abs + 1) * stride + n_abs];
    u32 lo;
    u32 hi = packbf(v0, v1, lo);
    g_wfrag[idx] = prec ? lo : hi;
}

// ---------------- projection pass (D^T via mma.sync) ----------------------
// MODE 0: Q -> Qimg (deferred epi, *scale). 1: K -> Kimg. 2: V -> vTimg.
// MODE 3: out-proj -> global (B operand = attn-out in Qimg).
template<int MODE>
__device__ void proj_pass(int tid, const float* __restrict__ bias, float scale,
                          u32* smu, int ct_base, float* outg)
{
    const int w = tid >> 5, lane = tid & 31;
    const int cg = w & 3, rg = w >> 2;
    const int g = lane >> 2, tid2 = lane & 3;
    const u32* Ah32 = smu + U_QH;
    const u32* Al32 = smu + U_QL;

    float acc[3][3][4];
#pragma unroll
    for (int c = 0; c < 3; c++)
#pragma unroll
        for (int rt = 0; rt < 3; rt++)
#pragma unroll
            for (int q = 0; q < 4; q++) acc[c][rt][q] = 0.0f;

    for (int k = 0; k < 12; k++) {
        u32 ah[3][4], al[3][4];
#pragma unroll
        for (int c = 0; c < 3; c++) {
            int ct = ct_base + cg * 3 + c;
            const u32* p = g_wfrag + (size_t)((ct * 12 + k) * 2) * 128 + lane * 4;
            *(uint4*)ah[c] = *(const uint4*)p;
            *(uint4*)al[c] = *(const uint4*)(p + 128);
        }
        u32 bh[3][2], bl[3][2];
#pragma unroll
        for (int rt = 0; rt < 3; rt++) {
            int row = (rg * 3 + rt) * 8 + g;
            int o = row * 100 + k * 8 + tid2;
            bh[rt][0] = Ah32[o]; bh[rt][1] = Ah32[o + 4];
            bl[rt][0] = Al32[o]; bl[rt][1] = Al32[o + 4];
        }
#pragma unroll
        for (int c = 0; c < 3; c++)
#pragma unroll
            for (int rt = 0; rt < 3; rt++) {
                mma16816(acc[c][rt], ah[c], bh[rt]);
                mma16816(acc[c][rt], ah[c], bl[rt]);
                mma16816(acc[c][rt], al[c], bh[rt]);
            }
    }
    if (MODE == 0) __syncthreads();   // all X reads done before Qimg overwrite

    if (MODE <= 1) {
        const u32 uh = (MODE == 0) ? U_QH : U_KH;
        const u32 ul = uh + 7200;
#pragma unroll
        for (int c = 0; c < 3; c++) {
            int ctl = cg * 3 + c;
#pragma unroll
            for (int rt = 0; rt < 3; rt++) {
                int rbase = (rg * 3 + rt) * 8;
#pragma unroll
                for (int q = 0; q < 4; q++) {
                    int feat = ctl * 16 + g + (q >> 1) * 8;
                    float v = (acc[c][rt][q] + __ldg(bias + feat)) * scale;
                    u32 hb, lb; bf_split(v, hb, lb);
                    u32 oh = __shfl_xor_sync(0xffffffffu, hb, 4);
                    u32 ol = __shfl_xor_sync(0xffffffffu, lb, 4);
                    if (!(g & 1)) {
                        int rr = rbase + tid2 * 2 + (q & 1);
                        int col = ctl * 8 + (g >> 1) + (q >> 1) * 4;
                        smu[uh + rr * 100 + col] = hb | (oh << 16);
                        smu[ul + rr * 100 + col] = lb | (ol << 16);
                    }
                }
            }
        }
    } else if (MODE == 2) {
#pragma unroll
        for (int c = 0; c < 3; c++) {
            int ctl = cg * 3 + c;
#pragma unroll
            for (int rt = 0; rt < 3; rt++) {
                int rbase = (rg * 3 + rt) * 8;
#pragma unroll
                for (int fp = 0; fp < 2; fp++) {
                    int F = ctl * 16 + g + fp * 8;
                    float b = __ldg(bias + F);
                    float v0 = acc[c][rt][fp * 2] + b;
                    float v1 = acc[c][rt][fp * 2 + 1] + b;
                    u32 lo; u32 hi = packbf(v0, v1, lo);
                    int tcol = (rbase >> 1) + tid2;
                    smu[U_VTH + F * 40 + tcol] = hi;
                    smu[U_VTL + F * 40 + tcol] = lo;
                }
            }
        }
    } else {
#pragma unroll
        for (int c = 0; c < 3; c++) {
            int ctl = cg * 3 + c;
#pragma unroll
            for (int rt = 0; rt < 3; rt++) {
                int rbase = (rg * 3 + rt) * 8;
#pragma unroll
                for (int q = 0; q < 4; q++) {
                    int feat = ctl * 16 + g + (q >> 1) * 8;
                    int rr = rbase + tid2 * 2 + (q & 1);
                    outg[rr * DIMX + feat] = acc[c][rt][q] + __ldg(bias + feat);
                }
            }
        }
    }
}

// ---------------- main kernel ----------------
__global__ __launch_bounds__(BLK, 1)
void earth_attn_kernel(
    const float* __restrict__ x,
    const float* __restrict__ mask,
    const float* __restrict__ bqkv,
    const float* __restrict__ bout,
    const float* __restrict__ tbl,
    float* __restrict__ out)
{
    extern __shared__ u32 smu[];
    float* smf = (float*)smu;
    const int c   = blockIdx.x;
    const int tid = threadIdx.x;
    const int wid = tid >> 5, lane = tid & 31;
    const int g = lane >> 2, tid2 = lane & 3;

    const int t_idx = c % TOWC;
    const int s_sh  = c / TOWC;
    const int m_idx = c % NWC;
    const float* maskg = mask + (size_t)m_idx * NSQ;
    const float* xsrc  = x + (size_t)c * (NTOK * DIMX);
    const float qscale = 0.1767766952966369f;
    u16* tb16 = (u16*)(smu + U_TB);

    // ---- init: zero image pads, stage X into Qimg region, stage bias table
    for (int i = tid; i < 768; i += BLK) {
        int F = i >> 2, cp = 36 + (i & 3);
        smu[U_VTH + F * 40 + cp] = 0;
        smu[U_VTL + F * 40 + cp] = 0;
    }
    for (int i = tid; i < 288; i += BLK) {
        int r = i >> 2, cp = 36 + (i & 3);
        smu[U_PH + r * 41 + cp] = 0;
        smu[U_PL + r * 41 + cp] = 0;
    }
    for (int i = tid; i < NTOK * 48; i += BLK) {
        int r = i / 48, c4 = i - r * 48;
        float4 v = ((const float4*)xsrc)[i];
        int o = r * 100 + c4 * 2;
        u32 lo0, lo1;
        u32 hi0 = packbf(v.x, v.y, lo0);
        u32 hi1 = packbf(v.z, v.w, lo1);
        smu[U_QH + o] = hi0; smu[U_QH + o + 1] = hi1;
        smu[U_QL + o] = lo0; smu[U_QL + o + 1] = lo1;
    }
    for (int i = tid; i < TBLROWS * NH; i += BLK) {
        int r = i / NH, hh = i - r * NH;
        tb16[i] = __bfloat16_as_ushort(
            __float2bfloat16(__ldg(tbl + (r * TOWC + t_idx) * NH + hh)));
    }
    __syncthreads();

    // ---- projections (V, K first; Q last with deferred epi over X region)
    proj_pass<2>(tid, bqkv + 384, 1.0f,   smu, 24, nullptr);
    proj_pass<1>(tid, bqkv + 192, 1.0f,   smu, 12, nullptr);
    proj_pass<0>(tid, bqkv,       qscale, smu, 0,  nullptr);
    __syncthreads();

    // ---- per-head attention, fully HMMA ----
    for (int h = 0; h < NH; h++) {
        // S = q_h k_h^T + bias + mask
        for (int t = wid; t < 45; t += 12) {
            int mt = t / 9, nt = t - mt * 9;
            int mb = (mt == 4) ? 56 : mt * 16;
            float acc[4] = {0.f, 0.f, 0.f, 0.f};
#pragma unroll
            for (int ks = 0; ks < 2; ks++) {
                int ab = U_QH + (mb + g) * 100 + h * 16 + ks * 8 + tid2;
                u32 ah[4] = { smu[ab], smu[ab + 800], smu[ab + 4], smu[ab + 804] };
                u32 al[4] = { smu[ab + 7200], smu[ab + 8000], smu[ab + 7204], smu[ab + 8004] };
                int kb = U_KH + (nt * 8 + g) * 100 + h * 16 + ks * 8 + tid2;
                u32 bh[2] = { smu[kb], smu[kb + 4] };
                u32 bl[2] = { smu[kb + 7200], smu[kb + 7204] };
                mma16816(acc, ah, bh);
                mma16816(acc, al, bh);
                mma16816(acc, ah, bl);
            }
            int qrow0 = mb + g, kcol = nt * 8 + tid2 * 2;
#pragma unroll
            for (int rh = 0; rh < 2; rh++) {
                if (mt == 4 && rh == 0) continue;
                int e = (qrow0 + rh * 8) * NTOK + kcol;
                float2 mv = *(const float2*)(maskg + e);
                float b0 = tbf(tb16[posv_of(e, s_sh) * NH + h]);
                float b1 = tbf(tb16[posv_of(e + 1, s_sh) * NH + h]);
                float2 o;
                o.x = acc[rh * 2]     + b0 + mv.x;
                o.y = acc[rh * 2 + 1] + b1 + mv.y;
                *(float2*)&smf[U_SB + e] = o;
            }
        }
        __syncthreads();

        // softmax (writes exp back to Sb, 1/sum to rs)
        for (int rr = wid; rr < NTOK; rr += 12) {
            float v0 = smf[U_SB + rr * 72 + lane];
            float v1 = smf[U_SB + rr * 72 + lane + 32];
            float v2 = (lane < 8) ? smf[U_SB + rr * 72 + lane + 64] : -1e30f;
            float m = fmaxf(v0, fmaxf(v1, v2));
#pragma unroll
            for (int o = 16; o > 0; o >>= 1) m = fmaxf(m, __shfl_xor_sync(0xffffffffu, m, o));
            v0 = __expf(v0 - m);
            v1 = __expf(v1 - m);
            v2 = (lane < 8) ? __expf(v2 - m) : 0.0f;
            float sum = v0 + v1 + v2;
#pragma unroll
            for (int o = 16; o > 0; o >>= 1) sum += __shfl_xor_sync(0xffffffffu, sum, o);
            smf[U_SB + rr * 72 + lane]      = v0;
            smf[U_SB + rr * 72 + lane + 32] = v1;
            if (lane < 8) smf[U_SB + rr * 72 + lane + 64] = v2;
            if (lane == 0) smf[U_RS + rr] = 1.0f / sum;
        }
        __syncthreads();

        // restage P = exp * (1/sum) as bf16 hi/lo image
        for (int i = tid; i < 2592; i += BLK) {
            int row = i / 36, j = i - row * 36;
            float2 v = *(const float2*)&smf[U_SB + row * 72 + j * 2];
            float rv = smf[U_RS + row];
            u32 lo; u32 hi = packbf(v.x * rv, v.y * rv, lo);
            smu[U_PH + row * 41 + j] = hi;
            smu[U_PL + row * 41 + j] = lo;
        }
        __syncthreads();

        // out_h = P @ v_h -> overwrite Qimg head-h columns
        for (int t = wid; t < 20; t += 12) {
            int mt = t >> 2, nt = t & 3;
            int mb = (mt == 4) ? 56 : mt * 16;
            float acc[4] = {0.f, 0.f, 0.f, 0.f};
#pragma unroll
            for (int ks = 0; ks < 5; ks++) {
                int ab = U_PH + (mb + g) * 41 + ks * 8 + tid2;
                u32 ah[4] = { smu[ab], smu[ab + 328], smu[ab + 4], smu[ab + 332] };
                u32 al[4] = { smu[ab + 2952], smu[ab + 3280], smu[ab + 2956], smu[ab + 3284] };
                int vb = U_VTH + (h * 32 + nt * 8 + g) * 40 + ks * 8 + tid2;
                u32 bh[2] = { smu[vb], smu[vb + 4] };
                u32 bl[2] = { smu[vb + 7680], smu[vb + 7684] };
                mma16816(acc, ah, bh);
                mma16816(acc, al, bh);
                mma16816(acc, ah, bl);
            }
            int col = h * 16 + nt * 4 + tid2;
            int row0 = mb + g;
            if (mt < 4) {
                u32 lo; u32 hi = packbf(acc[0], acc[1], lo);
                smu[U_QH + row0 * 100 + col] = hi;
                smu[U_QL + row0 * 100 + col] = lo;
            }
            {
                u32 lo; u32 hi = packbf(acc[2], acc[3], lo);
                smu[U_QH + (row0 + 8) * 100 + col] = hi;
                smu[U_QL + (row0 + 8) * 100 + col] = lo;
            }
        }
        // no sync needed: next QK^T touches different regions/cols;
        // Sb rewrite is fenced by the sync after the next QK^T epilogue
    }
    __syncthreads();

    // ---- out projection (B = attn-out in Qimg) -> global ----
    proj_pass<3>(tid, bout, 1.0f, smu, 36, out + (size_t)c * (NTOK * DIMX));
}

extern "C" void kernel_launch(void* const* d_in, const int* in_sizes, int n_in,
                              void* d_out, int out_size)
{
    const float* x    = (const float*)d_in[0];
    const float* mask = (const float*)d_in[1];
    const float* wqkv = (const float*)d_in[2];
    const float* bqkv = (const float*)d_in[3];
    const float* wout = (const float*)d_in[4];
    const float* bout = (const float*)d_in[5];
    const float* tbl  = (const float*)d_in[6];
    float* out = (float*)d_out;

    int B_ = in_sizes[0] / (NTOK * DIMX);   // 1860

    build_wfrags<<<576, 256>>>(wqkv, wout);

    cudaFuncSetAttribute(earth_attn_kernel,
                         cudaFuncAttributeMaxDynamicSharedMemorySize, SMEM_BYTES);
    earth_attn_kernel<<<B_, BLK, SMEM_BYTES>>>(x, mask, bqkv, bout, tbl, out);
}

// round 7
// speedup vs baseline: 1.0036x; 1.0036x over previous
#include <cuda_runtime.h>
#include <cuda_bf16.h>

// EarthAttention2D v6: full HMMA, register-resident attention (no syncs in
// head processing). One CTA per window; warp-independent (head, m-tile) tasks.

typedef unsigned long long u64;
typedef unsigned int u32;
typedef unsigned short u16;

#define NTOK 72
#define DIMX 192
#define NH 6
#define TOWC 31
#define NWC 30
#define BLK 384
#define NSQ 5184
#define TBLROWS 828

// u32-unit shared offsets
#define U_QH 0        // q / attn-out hi: [72][100]
#define U_QL 7200
#define U_KH 14400    // k hi: [72][100]
#define U_KL 21600
#define U_VTH 28800   // v^T hi: [192][40]
#define U_VTL 36480
#define U_MSK 44160   // mask slice f32 [5184]
#define U_PIDX 49344  // posv*6 u16 [5184] (2592 u32)
#define U_TB 51936    // bias slice bf16 [828*6] (2484 u32)
#define SMEM_BYTES (54420 * 4)   // 217680

// Pre-packed W^T A-fragments (hi/lo), register-exact m16n8k16 layout.
// u32 index = ((ct*12 + k)*2 + prec)*128 + lane*4 + r
__device__ u32 g_wfrag[147456];

// ---------------- helpers ----------------
__device__ __forceinline__ void mma16816(float* d, const u32* a, const u32* b) {
    asm("mma.sync.aligned.m16n8k16.row.col.f32.bf16.bf16.f32 "
        "{%0,%1,%2,%3}, {%4,%5,%6,%7}, {%8,%9}, {%0,%1,%2,%3};"
        : "+f"(d[0]), "+f"(d[1]), "+f"(d[2]), "+f"(d[3])
        : "r"(a[0]), "r"(a[1]), "r"(a[2]), "r"(a[3]), "r"(b[0]), "r"(b[1]));
}
__device__ __forceinline__ void mma16808(float* d, const u32* a, u32 b) {
    asm("mma.sync.aligned.m16n8k8.row.col.f32.bf16.bf16.f32 "
        "{%0,%1,%2,%3}, {%4,%5}, {%6}, {%0,%1,%2,%3};"
        : "+f"(d[0]), "+f"(d[1]), "+f"(d[2]), "+f"(d[3])
        : "r"(a[0]), "r"(a[1]), "r"(b));
}
__device__ __forceinline__ u32 packbf(float x0, float x1, u32& lo) {
    __nv_bfloat16 h0 = __float2bfloat16(x0), h1 = __float2bfloat16(x1);
    __nv_bfloat16 l0 = __float2bfloat16(x0 - __bfloat162float(h0));
    __nv_bfloat16 l1 = __float2bfloat16(x1 - __bfloat162float(h1));
    lo = (u32)__bfloat16_as_ushort(l0) | ((u32)__bfloat16_as_ushort(l1) << 16);
    return (u32)__bfloat16_as_ushort(h0) | ((u32)__bfloat16_as_ushort(h1) << 16);
}
__device__ __forceinline__ void bf_split(float v, u32& h, u32& l) {
    __nv_bfloat16 hb = __float2bfloat16(v);
    h = (u32)__bfloat16_as_ushort(hb);
    l = (u32)__bfloat16_as_ushort(__float2bfloat16(v - __bfloat162float(hb)));
}
__device__ __forceinline__ float tbf(u16 b) {
    return __bfloat162float(__ushort_as_bfloat16(b));
}

// ---------------- pre-kernel: pack W^T fragments ----------------
__global__ void build_wfrags(const float* __restrict__ wqkv,
                             const float* __restrict__ wout) {
    int idx = blockIdx.x * 256 + threadIdx.x;
    int r    = idx & 3;
    int lane = (idx >> 2) & 31;
    int prec = (idx >> 7) & 1;
    int rest = idx >> 8;
    int k  = rest % 12;
    int ct = rest / 12;
    int g = lane >> 2, tid2 = lane & 3;
    int i  = g + (r & 1) * 8;
    int kk = tid2 * 2 + (r >> 1) * 8;
    int k_abs = k * 16 + kk;
    const float* W; int stride, n_abs;
    if (ct < 36) { W = wqkv; stride = 576; n_abs = ct * 16 + i; }
    else         { W = wout; stride = 192; n_abs = (ct - 36) * 16 + i; }
    float v0 = W[(size_t)k_abs * stride + n_abs];
    float v1 = W[(size_t)(k_abs + 1) * stride + n_abs];
    u32 lo;
    u32 hi = packbf(v0, v1, lo);
    g_wfrag[idx] = prec ? lo : hi;
}

// ---------------- projection pass (validated in R4/R5) ----------------
// MODE 0: Q -> Qimg (deferred epi, *scale). 1: K -> Kimg. 2: V -> vTimg.
// MODE 3: out-proj -> global (B operand = attn-out in Qimg).
template<int MODE>
__device__ void proj_pass(int tid, const float* __restrict__ bias, float scale,
                          u32* smu, int ct_base, float* outg)
{
    const int w = tid >> 5, lane = tid & 31;
    const int cg = w & 3, rg = w >> 2;
    const int g = lane >> 2, tid2 = lane & 3;
    const u32* Ah32 = smu + U_QH;
    const u32* Al32 = smu + U_QL;

    float acc[3][3][4];
#pragma unroll
    for (int c = 0; c < 3; c++)
#pragma unroll
        for (int rt = 0; rt < 3; rt++)
#pragma unroll
            for (int q = 0; q < 4; q++) acc[c][rt][q] = 0.0f;

    for (int k = 0; k < 12; k++) {
        u32 ah[3][4], al[3][4];
#pragma unroll
        for (int c = 0; c < 3; c++) {
            int ct = ct_base + cg * 3 + c;
            const u32* p = g_wfrag + (size_t)((ct * 12 + k) * 2) * 128 + lane * 4;
            *(uint4*)ah[c] = *(const uint4*)p;
            *(uint4*)al[c] = *(const uint4*)(p + 128);
        }
        u32 bh[3][2], bl[3][2];
#pragma unroll
        for (int rt = 0; rt < 3; rt++) {
            int row = (rg * 3 + rt) * 8 + g;
            int o = row * 100 + k * 8 + tid2;
            bh[rt][0] = Ah32[o]; bh[rt][1] = Ah32[o + 4];
            bl[rt][0] = Al32[o]; bl[rt][1] = Al32[o + 4];
        }
#pragma unroll
        for (int c = 0; c < 3; c++)
#pragma unroll
            for (int rt = 0; rt < 3; rt++) {
                mma16816(acc[c][rt], ah[c], bh[rt]);
                mma16816(acc[c][rt], ah[c], bl[rt]);
                mma16816(acc[c][rt], al[c], bh[rt]);
            }
    }
    if (MODE == 0) __syncthreads();   // all X reads done before Qimg overwrite

    if (MODE <= 1) {
        const u32 uh = (MODE == 0) ? U_QH : U_KH;
        const u32 ul = uh + 7200;
#pragma unroll
        for (int c = 0; c < 3; c++) {
            int ctl = cg * 3 + c;
#pragma unroll
            for (int rt = 0; rt < 3; rt++) {
                int rbase = (rg * 3 + rt) * 8;
#pragma unroll
                for (int q = 0; q < 4; q++) {
                    int feat = ctl * 16 + g + (q >> 1) * 8;
                    float v = (acc[c][rt][q] + __ldg(bias + feat)) * scale;
                    u32 hb, lb; bf_split(v, hb, lb);
                    u32 oh = __shfl_xor_sync(0xffffffffu, hb, 4);
                    u32 ol = __shfl_xor_sync(0xffffffffu, lb, 4);
                    if (!(g & 1)) {
                        int rr = rbase + tid2 * 2 + (q & 1);
                        int col = ctl * 8 + (g >> 1) + (q >> 1) * 4;
                        smu[uh + rr * 100 + col] = hb | (oh << 16);
                        smu[ul + rr * 100 + col] = lb | (ol << 16);
                    }
                }
            }
        }
    } else if (MODE == 2) {
#pragma unroll
        for (int c = 0; c < 3; c++) {
            int ctl = cg * 3 + c;
#pragma unroll
            for (int rt = 0; rt < 3; rt++) {
                int rbase = (rg * 3 + rt) * 8;
#pragma unroll
                for (int fp = 0; fp < 2; fp++) {
                    int F = ctl * 16 + g + fp * 8;
                    float b = __ldg(bias + F);
                    float v0 = acc[c][rt][fp * 2] + b;
                    float v1 = acc[c][rt][fp * 2 + 1] + b;
                    u32 lo; u32 hi = packbf(v0, v1, lo);
                    int tcol = (rbase >> 1) + tid2;
                    smu[U_VTH + F * 40 + tcol] = hi;
                    smu[U_VTL + F * 40 + tcol] = lo;
                }
            }
        }
    } else {
#pragma unroll
        for (int c = 0; c < 3; c++) {
            int ctl = cg * 3 + c;
#pragma unroll
            for (int rt = 0; rt < 3; rt++) {
                int rbase = (rg * 3 + rt) * 8;
#pragma unroll
                for (int q = 0; q < 4; q++) {
                    int feat = ctl * 16 + g + (q >> 1) * 8;
                    int rr = rbase + tid2 * 2 + (q & 1);
                    outg[rr * DIMX + feat] = acc[c][rt][q] + __ldg(bias + feat);
                }
            }
        }
    }
}

// ---------------- main kernel ----------------
__global__ __launch_bounds__(BLK, 1)
void earth_attn_kernel(
    const float* __restrict__ x,
    const float* __restrict__ mask,
    const float* __restrict__ bqkv,
    const float* __restrict__ bout,
    const float* __restrict__ tbl,
    float* __restrict__ out)
{
    extern __shared__ u32 smu[];
    float* smf = (float*)smu;
    const int c   = blockIdx.x;
    const int tid = threadIdx.x;
    const int wid = tid >> 5, lane = tid & 31;
    const int g = lane >> 2, tid2 = lane & 3;

    const int t_idx = c % TOWC;
    const int s_sh  = c / TOWC;
    const int m_idx = c % NWC;
    const float* maskg = mask + (size_t)m_idx * NSQ;
    const float* xsrc  = x + (size_t)c * (NTOK * DIMX);
    const float qscale = 0.1767766952966369f;
    u16* tb16 = (u16*)(smu + U_TB);
    u16* pidx = (u16*)(smu + U_PIDX);

    // ---- init: stage X into Qimg region, mask, pidx, bias table ----
    for (int i = tid; i < NTOK * 48; i += BLK) {
        int r = i / 48, c4 = i - r * 48;
        float4 v = ((const float4*)xsrc)[i];
        int o = r * 100 + c4 * 2;
        u32 lo0, lo1;
        u32 hi0 = packbf(v.x, v.y, lo0);
        u32 hi1 = packbf(v.z, v.w, lo1);
        smu[U_QH + o] = hi0; smu[U_QH + o + 1] = hi1;
        smu[U_QL + o] = lo0; smu[U_QL + o + 1] = lo1;
    }
    for (int i = tid; i < NSQ; i += BLK) {
        smf[U_MSK + i] = __ldg(maskg + i);
        int p = (i * 60 + s_sh) % NSQ;
        int n2 = p / NTOK, m2 = p - n2 * NTOK;
        int n12 = n2 / 12, m12 = m2 / 12;
        int posv = (n12 + 6 * m12) * 23 + (n2 - n12 * 12) - (m2 - m12 * 12) + 11;
        pidx[i] = (u16)(posv * NH);
    }
    for (int i = tid; i < TBLROWS * NH; i += BLK) {
        int r = i / NH, hh = i - r * NH;
        tb16[i] = __bfloat16_as_ushort(
            __float2bfloat16(__ldg(tbl + (r * TOWC + t_idx) * NH + hh)));
    }
    __syncthreads();

    // ---- projections (V, K first; Q last with deferred epi over X region)
    proj_pass<2>(tid, bqkv + 384, 1.0f,   smu, 24, nullptr);
    proj_pass<1>(tid, bqkv + 192, 1.0f,   smu, 12, nullptr);
    proj_pass<0>(tid, bqkv,       qscale, smu, 0,  nullptr);
    __syncthreads();

    // ---- attention: warp-independent (head, m-tile) tasks, no syncs ----
    // units: u = wid + 12*s4; h = u % 6; stype = u / 6 (0,1,2 -> mt; 3 -> mt4 then mt3)
    for (int s4 = 0; s4 < 2; s4++) {
        int u = wid + s4 * 12;
        int h = u % 6;
        int stype = u / 6;
        int reps = (stype == 3) ? 2 : 1;
        for (int rep = 0; rep < reps; rep++) {
            int mt = (stype < 3) ? stype : (rep == 0 ? 4 : 3);
            int mb = (mt == 4) ? 56 : mt * 16;
            int r0 = mb + g, r1 = r0 + 8;

            // --- QK^T: acc[9][4] over 9 n-tiles ---
            float acc[9][4];
#pragma unroll
            for (int nt = 0; nt < 9; nt++)
#pragma unroll
                for (int q = 0; q < 4; q++) acc[nt][q] = 0.0f;

            u32 ah[2][4], al[2][4];
#pragma unroll
            for (int ks = 0; ks < 2; ks++) {
                int ab = U_QH + r0 * 100 + h * 16 + ks * 8 + tid2;
                ah[ks][0] = smu[ab];        ah[ks][1] = smu[ab + 800];
                ah[ks][2] = smu[ab + 4];    ah[ks][3] = smu[ab + 804];
                al[ks][0] = smu[ab + 7200]; al[ks][1] = smu[ab + 8000];
                al[ks][2] = smu[ab + 7204]; al[ks][3] = smu[ab + 8004];
            }
#pragma unroll
            for (int nt = 0; nt < 9; nt++) {
#pragma unroll
                for (int ks = 0; ks < 2; ks++) {
                    int kb = U_KH + (nt * 8 + g) * 100 + h * 16 + ks * 8 + tid2;
                    u32 bh[2] = { smu[kb], smu[kb + 4] };
                    u32 bl[2] = { smu[kb + 7200], smu[kb + 7204] };
                    mma16816(acc[nt], ah[ks], bh);
                    mma16816(acc[nt], al[ks], bh);
                    mma16816(acc[nt], ah[ks], bl);
                }
            }

            // --- bias + mask (in registers) ---
#pragma unroll
            for (int nt = 0; nt < 9; nt++) {
                int cc = nt * 8 + tid2 * 2;
                int e0 = r0 * 72 + cc, e1 = r1 * 72 + cc;
                float2 m0 = *(const float2*)&smf[U_MSK + e0];
                float2 m1 = *(const float2*)&smf[U_MSK + e1];
                acc[nt][0] += tbf(tb16[pidx[e0] + h])     + m0.x;
                acc[nt][1] += tbf(tb16[pidx[e0 + 1] + h]) + m0.y;
                acc[nt][2] += tbf(tb16[pidx[e1] + h])     + m1.x;
                acc[nt][3] += tbf(tb16[pidx[e1 + 1] + h]) + m1.y;
            }

            // --- softmax in registers (rows r0, r1 live in 4-lane quads) ---
            float mx0 = -1e30f, mx1 = -1e30f;
#pragma unroll
            for (int nt = 0; nt < 9; nt++) {
                mx0 = fmaxf(mx0, fmaxf(acc[nt][0], acc[nt][1]));
                mx1 = fmaxf(mx1, fmaxf(acc[nt][2], acc[nt][3]));
            }
#pragma unroll
            for (int o = 1; o <= 2; o <<= 1) {
                mx0 = fmaxf(mx0, __shfl_xor_sync(0xffffffffu, mx0, o));
                mx1 = fmaxf(mx1, __shfl_xor_sync(0xffffffffu, mx1, o));
            }
            float s0 = 0.f, s1 = 0.f;
#pragma unroll
            for (int nt = 0; nt < 9; nt++) {
                acc[nt][0] = __expf(acc[nt][0] - mx0);
                acc[nt][1] = __expf(acc[nt][1] - mx0);
                acc[nt][2] = __expf(acc[nt][2] - mx1);
                acc[nt][3] = __expf(acc[nt][3] - mx1);
                s0 += acc[nt][0] + acc[nt][1];
                s1 += acc[nt][2] + acc[nt][3];
            }
#pragma unroll
            for (int o = 1; o <= 2; o <<= 1) {
                s0 += __shfl_xor_sync(0xffffffffu, s0, o);
                s1 += __shfl_xor_sync(0xffffffffu, s1, o);
            }
            float rv0 = 1.0f / s0, rv1 = 1.0f / s1;

            // --- pack P into A-fragments (register-to-register) ---
            u32 ph[4][4], pl[4][4], ph8[2], pl8[2];
#pragma unroll
            for (int j = 0; j < 4; j++) {
                ph[j][0] = packbf(acc[2*j][0] * rv0,   acc[2*j][1] * rv0,   pl[j][0]);
                ph[j][1] = packbf(acc[2*j][2] * rv1,   acc[2*j][3] * rv1,   pl[j][1]);
                ph[j][2] = packbf(acc[2*j+1][0] * rv0, acc[2*j+1][1] * rv0, pl[j][2]);
                ph[j][3] = packbf(acc[2*j+1][2] * rv1, acc[2*j+1][3] * rv1, pl[j][3]);
            }
            ph8[0] = packbf(acc[8][0] * rv0, acc[8][1] * rv0, pl8[0]);
            ph8[1] = packbf(acc[8][2] * rv1, acc[8][3] * rv1, pl8[1]);

            // --- AV: out = P @ v_h -> write Qimg head-h cols (own rows) ---
            bool w0 = (mt != 4);
#pragma unroll
            for (int nt2 = 0; nt2 < 4; nt2++) {
                float o2[4] = {0.f, 0.f, 0.f, 0.f};
                int vbase = U_VTH + (h * 32 + nt2 * 8 + g) * 40;
#pragma unroll
                for (int j = 0; j < 4; j++) {
                    u32 bh[2] = { smu[vbase + j * 8 + tid2], smu[vbase + j * 8 + 4 + tid2] };
                    u32 bl[2] = { smu[vbase + 7680 + j * 8 + tid2], smu[vbase + 7680 + j * 8 + 4 + tid2] };
                    mma16816(o2, ph[j], bh);
                    mma16816(o2, pl[j], bh);
                    mma16816(o2, ph[j], bl);
                }
                {
                    u32 b8h = smu[vbase + 32 + tid2];
                    u32 b8l = smu[vbase + 7680 + 32 + tid2];
                    mma16808(o2, ph8, b8h);
                    mma16808(o2, pl8, b8h);
                    mma16808(o2, ph8, b8l);
                }
                int col = h * 16 + nt2 * 4 + tid2;
                u32 lo; u32 hi = packbf(o2[0], o2[1], lo);
                if (w0) {
                    smu[U_QH + r0 * 100 + col] = hi;
                    smu[U_QL + r0 * 100 + col] = lo;
                }
                hi = packbf(o2[2], o2[3], lo);
                smu[U_QH + r1 * 100 + col] = hi;
                smu[U_QL + r1 * 100 + col] = lo;
            }
        }
    }
    __syncthreads();

    // ---- out projection (B = attn-out in Qimg) -> global ----
    proj_pass<3>(tid, bout, 1.0f, smu, 36, out + (size_t)c * (NTOK * DIMX));
}

extern "C" void kernel_launch(void* const* d_in, const int* in_sizes, int n_in,
                              void* d_out, int out_size)
{
    const float* x    = (const float*)d_in[0];
    const float* mask = (const float*)d_in[1];
    const float* wqkv = (const float*)d_in[2];
    const float* bqkv = (const float*)d_in[3];
    const float* wout = (const float*)d_in[4];
    const float* bout = (const float*)d_in[5];
    const float* tbl  = (const float*)d_in[6];
    float* out = (float*)d_out;

    int B_ = in_sizes[0] / (NTOK * DIMX);   // 1860

    build_wfrags<<<576, 256>>>(wqkv, wout);

    cudaFuncSetAttribute(earth_attn_kernel,
                         cudaFuncAttributeMaxDynamicSharedMemorySize, SMEM_BYTES);
    earth_attn_kernel<<<B_, BLK, SMEM_BYTES>>>(x, mask, bqkv, bout, tbl, out);
}

// round 9
// speedup vs baseline: 1.5942x; 1.5885x over previous
#include <cuda_runtime.h>
#include <cuda_bf16.h>

// EarthAttention2D v7: full HMMA, register-resident attention, software-
// pipelined projection k-loop (depth-1 prefetch of W fragments from L2).

typedef unsigned long long u64;
typedef unsigned int u32;
typedef unsigned short u16;

#define NTOK 72
#define DIMX 192
#define NH 6
#define TOWC 31
#define NWC 30
#define BLK 384
#define NSQ 5184
#define TBLROWS 828

// u32-unit shared offsets
#define U_QH 0        // q / attn-out hi: [72][100]
#define U_QL 7200
#define U_KH 14400    // k hi: [72][100]
#define U_KL 21600
#define U_VTH 28800   // v^T hi: [192][40]
#define U_VTL 36480
#define U_PIDX 44160  // posv*6 u16 [5184] (2592 u32)
#define U_TB 46752    // bias slice bf16 [828*6] (2484 u32)
#define SMEM_BYTES (49236 * 4)   // 196944

// Pre-packed W^T A-fragments (hi/lo), register-exact m16n8k16 layout.
// u32 index = ((ct*12 + k)*2 + prec)*128 + lane*4 + r
__device__ u32 g_wfrag[147456];

// ---------------- helpers ----------------
__device__ __forceinline__ void mma16816(float* d, const u32* a, const u32* b) {
    asm("mma.sync.aligned.m16n8k16.row.col.f32.bf16.bf16.f32 "
        "{%0,%1,%2,%3}, {%4,%5,%6,%7}, {%8,%9}, {%0,%1,%2,%3};"
        : "+f"(d[0]), "+f"(d[1]), "+f"(d[2]), "+f"(d[3])
        : "r"(a[0]), "r"(a[1]), "r"(a[2]), "r"(a[3]), "r"(b[0]), "r"(b[1]));
}
__device__ __forceinline__ void mma16808(float* d, const u32* a, u32 b) {
    asm("mma.sync.aligned.m16n8k8.row.col.f32.bf16.bf16.f32 "
        "{%0,%1,%2,%3}, {%4,%5}, {%6}, {%0,%1,%2,%3};"
        : "+f"(d[0]), "+f"(d[1]), "+f"(d[2]), "+f"(d[3])
        : "r"(a[0]), "r"(a[1]), "r"(b));
}
__device__ __forceinline__ u32 packbf(float x0, float x1, u32& lo) {
    __nv_bfloat16 h0 = __float2bfloat16(x0), h1 = __float2bfloat16(x1);
    __nv_bfloat16 l0 = __float2bfloat16(x0 - __bfloat162float(h0));
    __nv_bfloat16 l1 = __float2bfloat16(x1 - __bfloat162float(h1));
    lo = (u32)__bfloat16_as_ushort(l0) | ((u32)__bfloat16_as_ushort(l1) << 16);
    return (u32)__bfloat16_as_ushort(h0) | ((u32)__bfloat16_as_ushort(h1) << 16);
}
__device__ __forceinline__ void bf_split(float v, u32& h, u32& l) {
    __nv_bfloat16 hb = __float2bfloat16(v);
    h = (u32)__bfloat16_as_ushort(hb);
    l = (u32)__bfloat16_as_ushort(__float2bfloat16(v - __bfloat162float(hb)));
}
__device__ __forceinline__ float tbf(u16 b) {
    return __bfloat162float(__ushort_as_bfloat16(b));
}

// ---------------- pre-kernel: pack W^T fragments ----------------
__global__ void build_wfrags(const float* __restrict__ wqkv,
                             const float* __restrict__ wout) {
    int idx = blockIdx.x * 256 + threadIdx.x;
    int r    = idx & 3;
    int lane = (idx >> 2) & 31;
    int prec = (idx >> 7) & 1;
    int rest = idx >> 8;
    int k  = rest % 12;
    int ct = rest / 12;
    int g = lane >> 2, tid2 = lane & 3;
    int i  = g + (r & 1) * 8;
    int kk = tid2 * 2 + (r >> 1) * 8;
    int k_abs = k * 16 + kk;
    const float* W; int stride, n_abs;
    if (ct < 36) { W = wqkv; stride = 576; n_abs = ct * 16 + i; }
    else         { W = wout; stride = 192; n_abs = (ct - 36) * 16 + i; }
    float v0 = W[(size_t)k_abs * stride + n_abs];
    float v1 = W[(size_t)(k_abs + 1) * stride + n_abs];
    u32 lo;
    u32 hi = packbf(v0, v1, lo);
    g_wfrag[idx] = prec ? lo : hi;
}

// ---------------- projection pass: software-pipelined k-loop --------------
// MODE 0: Q -> Qimg (deferred epi, *scale). 1: K -> Kimg. 2: V -> vTimg.
// MODE 3: out-proj -> global (B operand = attn-out in Qimg).
template<int MODE>
__device__ void proj_pass(int tid, const float* __restrict__ bias, float scale,
                          u32* smu, int ct_base, float* outg)
{
    const int w = tid >> 5, lane = tid & 31;
    const int cg = w & 3, rg = w >> 2;
    const int g = lane >> 2, tid2 = lane & 3;
    const u32* Ah32 = smu + U_QH;
    const u32* Al32 = smu + U_QL;

    float acc[3][3][4];
#pragma unroll
    for (int c = 0; c < 3; c++)
#pragma unroll
        for (int rt = 0; rt < 3; rt++)
#pragma unroll
            for (int q = 0; q < 4; q++) acc[c][rt][q] = 0.0f;

    u32 ah[2][3][4], al[2][3][4], bh[2][3][2], bl[2][3][2];

    // prologue: load k=0 into buffer 0
#pragma unroll
    for (int c = 0; c < 3; c++) {
        int ct = ct_base + cg * 3 + c;
        const u32* p = g_wfrag + (size_t)((ct * 12) * 2) * 128 + lane * 4;
        *(uint4*)ah[0][c] = *(const uint4*)p;
        *(uint4*)al[0][c] = *(const uint4*)(p + 128);
    }
#pragma unroll
    for (int rt = 0; rt < 3; rt++) {
        int row = (rg * 3 + rt) * 8 + g;
        int o = row * 100 + tid2;
        bh[0][rt][0] = Ah32[o]; bh[0][rt][1] = Ah32[o + 4];
        bl[0][rt][0] = Al32[o]; bl[0][rt][1] = Al32[o + 4];
    }

#pragma unroll
    for (int k = 0; k < 12; k++) {
        const int cur = k & 1, nxt = cur ^ 1;
        if (k < 11) {
            const int kn = k + 1;
#pragma unroll
            for (int c = 0; c < 3; c++) {
                int ct = ct_base + cg * 3 + c;
                const u32* p = g_wfrag + (size_t)((ct * 12 + kn) * 2) * 128 + lane * 4;
                *(uint4*)ah[nxt][c] = *(const uint4*)p;
                *(uint4*)al[nxt][c] = *(const uint4*)(p + 128);
            }
#pragma unroll
            for (int rt = 0; rt < 3; rt++) {
                int row = (rg * 3 + rt) * 8 + g;
                int o = row * 100 + kn * 8 + tid2;
                bh[nxt][rt][0] = Ah32[o]; bh[nxt][rt][1] = Ah32[o + 4];
                bl[nxt][rt][0] = Al32[o]; bl[nxt][rt][1] = Al32[o + 4];
            }
        }
#pragma unroll
        for (int c = 0; c < 3; c++)
#pragma unroll
            for (int rt = 0; rt < 3; rt++) {
                mma16816(acc[c][rt], ah[cur][c], bh[cur][rt]);
                mma16816(acc[c][rt], al[cur][c], bh[cur][rt]);
                mma16816(acc[c][rt], ah[cur][c], bl[cur][rt]);
            }
    }
    if (MODE == 0) __syncthreads();   // all X reads done before Qimg overwrite

    if (MODE <= 1) {
        const u32 uh = (MODE == 0) ? U_QH : U_KH;
        const u32 ul = uh + 7200;
#pragma unroll
        for (int c = 0; c < 3; c++) {
            int ctl = cg * 3 + c;
#pragma unroll
            for (int rt = 0; rt < 3; rt++) {
                int rbase = (rg * 3 + rt) * 8;
#pragma unroll
                for (int q = 0; q < 4; q++) {
                    int feat = ctl * 16 + g + (q >> 1) * 8;
                    float v = (acc[c][rt][q] + __ldg(bias + feat)) * scale;
                    u32 hb, lb; bf_split(v, hb, lb);
                    u32 oh = __shfl_xor_sync(0xffffffffu, hb, 4);
                    u32 ol = __shfl_xor_sync(0xffffffffu, lb, 4);
                    if (!(g & 1)) {
                        int rr = rbase + tid2 * 2 + (q & 1);
                        int col = ctl * 8 + (g >> 1) + (q >> 1) * 4;
                        smu[uh + rr * 100 + col] = hb | (oh << 16);
                        smu[ul + rr * 100 + col] = lb | (ol << 16);
                    }
                }
            }
        }
    } else if (MODE == 2) {
#pragma unroll
        for (int c = 0; c < 3; c++) {
            int ctl = cg * 3 + c;
#pragma unroll
            for (int rt = 0; rt < 3; rt++) {
                int rbase = (rg * 3 + rt) * 8;
#pragma unroll
                for (int fp = 0; fp < 2; fp++) {
                    int F = ctl * 16 + g + fp * 8;
                    float b = __ldg(bias + F);
                    float v0 = acc[c][rt][fp * 2] + b;
                    float v1 = acc[c][rt][fp * 2 + 1] + b;
                    u32 lo; u32 hi = packbf(v0, v1, lo);
                    int tcol = (rbase >> 1) + tid2;
                    smu[U_VTH + F * 40 + tcol] = hi;
                    smu[U_VTL + F * 40 + tcol] = lo;
                }
            }
        }
    } else {
#pragma unroll
        for (int c = 0; c < 3; c++) {
            int ctl = cg * 3 + c;
#pragma unroll
            for (int rt = 0; rt < 3; rt++) {
                int rbase = (rg * 3 + rt) * 8;
#pragma unroll
                for (int q = 0; q < 4; q++) {
                    int feat = ctl * 16 + g + (q >> 1) * 8;
                    int rr = rbase + tid2 * 2 + (q & 1);
                    outg[rr * DIMX + feat] = acc[c][rt][q] + __ldg(bias + feat);
                }
            }
        }
    }
}

// ---------------- main kernel ----------------
__global__ __launch_bounds__(BLK, 1)
void earth_attn_kernel(
    const float* __restrict__ x,
    const float* __restrict__ mask,
    const float* __restrict__ bqkv,
    const float* __restrict__ bout,
    const float* __restrict__ tbl,
    float* __restrict__ out)
{
    extern __shared__ u32 smu[];
    const int c   = blockIdx.x;
    const int tid = threadIdx.x;
    const int wid = tid >> 5, lane = tid & 31;
    const int g = lane >> 2, tid2 = lane & 3;

    const int t_idx = c % TOWC;
    const int s_sh  = c / TOWC;
    const int m_idx = c % NWC;
    const float* maskg = mask + (size_t)m_idx * NSQ;
    const float* xsrc  = x + (size_t)c * (NTOK * DIMX);
    const float qscale = 0.1767766952966369f;
    u16* tb16 = (u16*)(smu + U_TB);
    u16* pidx = (u16*)(smu + U_PIDX);

    // ---- init: stage X into Qimg region, pidx, bias table ----
    for (int i = tid; i < NTOK * 48; i += BLK) {
        int r = i / 48, c4 = i - r * 48;
        float4 v = ((const float4*)xsrc)[i];
        int o = r * 100 + c4 * 2;
        u32 lo0, lo1;
        u32 hi0 = packbf(v.x, v.y, lo0);
        u32 hi1 = packbf(v.z, v.w, lo1);
        smu[U_QH + o] = hi0; smu[U_QH + o + 1] = hi1;
        smu[U_QL + o] = lo0; smu[U_QL + o + 1] = lo1;
    }
    for (int i = tid; i < NSQ; i += BLK) {
        int p = (i * 60 + s_sh) % NSQ;
        int n2 = p / NTOK, m2 = p - n2 * NTOK;
        int n12 = n2 / 12, m12 = m2 / 12;
        int posv = (n12 + 6 * m12) * 23 + (n2 - n12 * 12) - (m2 - m12 * 12) + 11;
        pidx[i] = (u16)(posv * NH);
    }
    for (int i = tid; i < TBLROWS * NH; i += BLK) {
        int r = i / NH, hh = i - r * NH;
        tb16[i] = __bfloat16_as_ushort(
            __float2bfloat16(__ldg(tbl + (r * TOWC + t_idx) * NH + hh)));
    }
    __syncthreads();

    // ---- projections (V, K first; Q last with deferred epi over X region)
    proj_pass<2>(tid, bqkv + 384, 1.0f,   smu, 24, nullptr);
    proj_pass<1>(tid, bqkv + 192, 1.0f,   smu, 12, nullptr);
    proj_pass<0>(tid, bqkv,       qscale, smu, 0,  nullptr);
    __syncthreads();

    // ---- attention: warp-independent (head, m-tile) tasks, no syncs ----
    for (int s4 = 0; s4 < 2; s4++) {
        int u = wid + s4 * 12;
        int h = u % 6;
        int stype = u / 6;
        int reps = (stype == 3) ? 2 : 1;
        for (int rep = 0; rep < reps; rep++) {
            int mt = (stype < 3) ? stype : (rep == 0 ? 4 : 3);
            int mb = (mt == 4) ? 56 : mt * 16;
            int r0 = mb + g, r1 = r0 + 8;

            // --- QK^T ---
            float acc[9][4];
#pragma unroll
            for (int nt = 0; nt < 9; nt++)
#pragma unroll
                for (int q = 0; q < 4; q++) acc[nt][q] = 0.0f;

            u32 ah[2][4], al[2][4];
#pragma unroll
            for (int ks = 0; ks < 2; ks++) {
                int ab = U_QH + r0 * 100 + h * 16 + ks * 8 + tid2;
                ah[ks][0] = smu[ab];        ah[ks][1] = smu[ab + 800];
                ah[ks][2] = smu[ab + 4];    ah[ks][3] = smu[ab + 804];
                al[ks][0] = smu[ab + 7200]; al[ks][1] = smu[ab + 8000];
                al[ks][2] = smu[ab + 7204]; al[ks][3] = smu[ab + 8004];
            }
#pragma unroll
            for (int nt = 0; nt < 9; nt++) {
#pragma unroll
                for (int ks = 0; ks < 2; ks++) {
                    int kb = U_KH + (nt * 8 + g) * 100 + h * 16 + ks * 8 + tid2;
                    u32 bh[2] = { smu[kb], smu[kb + 4] };
                    u32 bl[2] = { smu[kb + 7200], smu[kb + 7204] };
                    mma16816(acc[nt], ah[ks], bh);
                    mma16816(acc[nt], al[ks], bh);
                    mma16816(acc[nt], ah[ks], bl);
                }
            }

            // --- bias (smem) + mask (direct from L2) ---
#pragma unroll
            for (int nt = 0; nt < 9; nt++) {
                int cc = nt * 8 + tid2 * 2;
                int e0 = r0 * 72 + cc, e1 = r1 * 72 + cc;
                float2 m0 = __ldg((const float2*)(maskg + e0));
                float2 m1 = __ldg((const float2*)(maskg + e1));
                acc[nt][0] += tbf(tb16[pidx[e0] + h])     + m0.x;
                acc[nt][1] += tbf(tb16[pidx[e0 + 1] + h]) + m0.y;
                acc[nt][2] += tbf(tb16[pidx[e1] + h])     + m1.x;
                acc[nt][3] += tbf(tb16[pidx[e1 + 1] + h]) + m1.y;
            }

            // --- softmax in registers ---
            float mx0 = -1e30f, mx1 = -1e30f;
#pragma unroll
            for (int nt = 0; nt < 9; nt++) {
                mx0 = fmaxf(mx0, fmaxf(acc[nt][0], acc[nt][1]));
                mx1 = fmaxf(mx1, fmaxf(acc[nt][2], acc[nt][3]));
            }
#pragma unroll
            for (int o = 1; o <= 2; o <<= 1) {
                mx0 = fmaxf(mx0, __shfl_xor_sync(0xffffffffu, mx0, o));
                mx1 = fmaxf(mx1, __shfl_xor_sync(0xffffffffu, mx1, o));
            }
            float s0 = 0.f, s1 = 0.f;
#pragma unroll
            for (int nt = 0; nt < 9; nt++) {
                acc[nt][0] = __expf(acc[nt][0] - mx0);
                acc[nt][1] = __expf(acc[nt][1] - mx0);
                acc[nt][2] = __expf(acc[nt][2] - mx1);
                acc[nt][3] = __expf(acc[nt][3] - mx1);
                s0 += acc[nt][0] + acc[nt][1];
                s1 += acc[nt][2] + acc[nt][3];
            }
#pragma unroll
            for (int o = 1; o <= 2; o <<= 1) {
                s0 += __shfl_xor_sync(0xffffffffu, s0, o);
                s1 += __shfl_xor_sync(0xffffffffu, s1, o);
            }
            float rv0 = 1.0f / s0, rv1 = 1.0f / s1;

            // --- pack P into A-fragments (register-to-register) ---
            u32 ph[4][4], pl[4][4], ph8[2], pl8[2];
#pragma unroll
            for (int j = 0; j < 4; j++) {
                ph[j][0] = packbf(acc[2*j][0] * rv0,   acc[2*j][1] * rv0,   pl[j][0]);
                ph[j][1] = packbf(acc[2*j][2] * rv1,   acc[2*j][3] * rv1,   pl[j][1]);
                ph[j][2] = packbf(acc[2*j+1][0] * rv0, acc[2*j+1][1] * rv0, pl[j][2]);
                ph[j][3] = packbf(acc[2*j+1][2] * rv1, acc[2*j+1][3] * rv1, pl[j][3]);
            }
            ph8[0] = packbf(acc[8][0] * rv0, acc[8][1] * rv0, pl8[0]);
            ph8[1] = packbf(acc[8][2] * rv1, acc[8][3] * rv1, pl8[1]);

            // --- AV: out = P @ v_h -> write Qimg head-h cols (own rows) ---
            bool w0 = (mt != 4);
#pragma unroll
            for (int nt2 = 0; nt2 < 4; nt2++) {
                float o2[4] = {0.f, 0.f, 0.f, 0.f};
                int vbase = U_VTH + (h * 32 + nt2 * 8 + g) * 40;
#pragma unroll
                for (int j = 0; j < 4; j++) {
                    u32 bh[2] = { smu[vbase + j * 8 + tid2], smu[vbase + j * 8 + 4 + tid2] };
                    u32 bl[2] = { smu[vbase + 7680 + j * 8 + tid2], smu[vbase + 7680 + j * 8 + 4 + tid2] };
                    mma16816(o2, ph[j], bh);
                    mma16816(o2, pl[j], bh);
                    mma16816(o2, ph[j], bl);
                }
                {
                    u32 b8h = smu[vbase + 32 + tid2];
                    u32 b8l = smu[vbase + 7680 + 32 + tid2];
                    mma16808(o2, ph8, b8h);
                    mma16808(o2, pl8, b8h);
                    mma16808(o2, ph8, b8l);
                }
                int col = h * 16 + nt2 * 4 + tid2;
                u32 lo; u32 hi = packbf(o2[0], o2[1], lo);
                if (w0) {
                    smu[U_QH + r0 * 100 + col] = hi;
                    smu[U_QL + r0 * 100 + col] = lo;
                }
                hi = packbf(o2[2], o2[3], lo);
                smu[U_QH + r1 * 100 + col] = hi;
                smu[U_QL + r1 * 100 + col] = lo;
            }
        }
    }
    __syncthreads();

    // ---- out projection (B = attn-out in Qimg) -> global ----
    proj_pass<3>(tid, bout, 1.0f, smu, 36, out + (size_t)c * (NTOK * DIMX));
}

extern "C" void kernel_launch(void* const* d_in, const int* in_sizes, int n_in,
                              void* d_out, int out_size)
{
    const float* x    = (const float*)d_in[0];
    const float* mask = (const float*)d_in[1];
    const float* wqkv = (const float*)d_in[2];
    const float* bqkv = (const float*)d_in[3];
    const float* wout = (const float*)d_in[4];
    const float* bout = (const float*)d_in[5];
    const float* tbl  = (const float*)d_in[6];
    float* out = (float*)d_out;

    int B_ = in_sizes[0] / (NTOK * DIMX);   // 1860

    build_wfrags<<<576, 256>>>(wqkv, wout);

    cudaFuncSetAttribute(earth_attn_kernel,
                         cudaFuncAttributeMaxDynamicSharedMemorySize, SMEM_BYTES);
    earth_attn_kernel<<<B_, BLK, SMEM_BYTES>>>(x, mask, bqkv, bout, tbl, out);
}